// round 4
// baseline (speedup 1.0000x reference)
#include <cuda_runtime.h>
#include <cstdint>
#include <cstddef>

#define NHEADS   8
#define MEMDIM   1024
#define MEMSIZE  32768
#define TZ       64
#define ZSPLIT   2
#define ZPER     (MEMSIZE / ZSPLIT)   // 16384
#define NIT      (ZPER / TZ)          // 256

// smem layout (bytes from base): K/V double buffers + Q staging
#define OFF_K0   0u
#define OFF_K1   32768u
#define OFF_V0   65536u
#define OFF_V1   98304u
#define OFF_Q    131072u
#define SMEM_BYTES (131072u + 65536u)   // 192 KB

__device__ float g_O[ZSPLIT * 64 * 128 * 128];   // [zs*64+hm][m][d] unnormalized
__device__ float g_R[ZSPLIT * 64 * 128];         // row sums

// ---------------- helpers ----------------
__device__ __forceinline__ uint32_t smem_u32(const void* p) {
    uint32_t a;
    asm("{ .reg .u64 t; cvta.to.shared.u64 t, %1; cvt.u32.u64 %0, t; }" : "=r"(a) : "l"(p));
    return a;
}

#define CP16(dst, src) \
    asm volatile("cp.async.cg.shared.global [%0], [%1], 16;" :: "r"(dst), "l"(src) : "memory")
#define CP_COMMIT() asm volatile("cp.async.commit_group;" ::: "memory")
#define CP_WAIT(n)  asm volatile("cp.async.wait_group %0;" :: "n"(n) : "memory")

#define LDSM4(r0, r1, r2, r3, a) \
    asm volatile("ldmatrix.sync.aligned.m8n8.x4.shared.b16 {%0,%1,%2,%3}, [%4];" \
        : "=r"(r0), "=r"(r1), "=r"(r2), "=r"(r3) : "r"(a))

#define MMA(c, a, b0, b1) \
    asm volatile("mma.sync.aligned.m16n8k8.row.col.f32.tf32.tf32.f32 " \
        "{%0,%1,%2,%3}, {%4,%5,%6,%7}, {%8,%9}, {%0,%1,%2,%3};" \
        : "+f"((c)[0]), "+f"((c)[1]), "+f"((c)[2]), "+f"((c)[3]) \
        : "r"((a)[0]), "r"((a)[1]), "r"((a)[2]), "r"((a)[3]), "r"(b0), "r"(b1))

__device__ __forceinline__ uint32_t cvt_tf32(float f) {
    uint32_t t;
    asm("cvt.rna.tf32.f32 %0, %1;" : "=r"(t) : "f"(f));
    return t;
}

// ============================================================
// main kernel: one CTA = (zsplit, head, mtile); 256 threads
// ============================================================
__global__ void __launch_bounds__(256, 1)
kvmem_main(const float* __restrict__ hin, const float* __restrict__ keys,
           const float* __restrict__ values) {
    extern __shared__ __align__(1024) char dsm[];
    const uint32_t base = smem_u32(dsm);

    const int tid  = threadIdx.x;
    const int lane = tid & 31;
    const int w    = tid >> 5;

    const int cta  = blockIdx.x;          // 0..127
    const int zs   = cta >> 6;
    const int hm   = cta & 63;
    const int head = hm >> 3, mt = hm & 7;
    const int z0base = zs * ZPER;
    const int tok0   = mt * 128;

    const uint32_t Kb[2] = { base + OFF_K0, base + OFF_K1 };
    const uint32_t Vb[2] = { base + OFF_V0, base + OFF_V1 };
    const uint32_t Qs    = base + OFF_Q;

    // ---------- prologue: stage Q (128x128 f32, swizzled rows of 512B) ----------
    {
        const float* qsrc = hin + (size_t)tok0 * MEMDIM + head * 128;
#pragma unroll
        for (int c = tid; c < 4096; c += 256) {
            int m = c >> 5, dc = c & 31;                        // 32 16B-chunks per row
            uint32_t dst = Qs + m * 512 + (uint32_t)((dc ^ (m & 7)) << 4);
            CP16(dst, qsrc + (size_t)m * MEMDIM + dc * 4);
        }
        CP_COMMIT();
    }

    auto loadK = [&](int it, int b) {
        const float* ksrc = keys + (size_t)(z0base + it * TZ) * MEMDIM + head * 128;
#pragma unroll
        for (int c = tid; c < 2048; c += 256) {
            int z = c >> 5, dc = c & 31;                        // 64 rows x 512B
            uint32_t dst = Kb[b] + z * 512 + (uint32_t)((dc ^ (z & 7)) << 4);
            CP16(dst, ksrc + (size_t)z * MEMDIM + dc * 4);
        }
    };
    auto loadV = [&](int it, int b) {
        const float* vsrc = values + (size_t)(head * 128) * MEMSIZE + z0base + it * TZ;
#pragma unroll
        for (int c = tid; c < 2048; c += 256) {
            int d = c >> 4, zc = c & 15;                        // 128 rows x 256B
            uint32_t dst = Vb[b] + d * 256 + (uint32_t)((zc ^ (d & 7)) << 4);
            CP16(dst, vsrc + (size_t)d * MEMSIZE + zc * 4);
        }
    };

    loadK(0, 0); loadV(0, 0); CP_COMMIT();
    loadK(1, 1); loadV(1, 1); CP_COMMIT();

    // ---------- load Q a-frags to registers (tf32) ----------
    uint32_t qa[16][4];
    CP_WAIT(2);                 // Q landed
    __syncthreads();
    {
        const int m0   = w * 16;
        const int trow = lane & 7, tile = lane >> 3;
        const int row  = m0 + trow + (tile & 1) * 8;
#pragma unroll
        for (int s = 0; s < 16; s++) {
            uint32_t a = Qs + row * 512 +
                         (uint32_t)((((2 * s + (tile >> 1)) ^ (row & 7))) << 4);
            LDSM4(qa[s][0], qa[s][1], qa[s][2], qa[s][3], a);
        }
#pragma unroll
        for (int s = 0; s < 16; s++)
#pragma unroll
            for (int k = 0; k < 4; k++)
                qa[s][k] = cvt_tf32(__uint_as_float(qa[s][k]));
    }

    // output accumulators: warp's 16 rows x 128 d
    float oc[16][4];
#pragma unroll
    for (int j = 0; j < 16; j++) { oc[j][0] = oc[j][1] = oc[j][2] = oc[j][3] = 0.f; }
    float rs0 = 0.f, rs1 = 0.f;   // row sums for rows r0, r0+8

    const int lr = lane & 7, hi = lane >> 3;
    const int q4 = lane & 3;
    const int src_lo = (lane & ~3) | (q4 >> 1);
    const int src_hi = src_lo + 2;
    const bool sel = (q4 & 1);

#pragma unroll 1
    for (int i = 0; i < NIT; i++) {
        const int b = i & 1;
        CP_WAIT(1);               // buffer b data for iter i landed
        __syncthreads();
        const uint32_t kb = Kb[b], vb = Vb[b];

        // ---------- GEMM1: S[16m x 64z] = Q . K^T ----------
        float sc[8][4];
#pragma unroll
        for (int j = 0; j < 8; j++) {
            sc[j][0] = sc[j][1] = sc[j][2] = sc[j][3] = 0.f;
#pragma unroll
            for (int s2 = 0; s2 < 8; s2++) {
                uint32_t r0, r1, r2, r3;
                uint32_t a = kb + (8 * j + lr) * 512 +
                             (uint32_t)((((4 * s2 + hi) ^ lr)) << 4);
                LDSM4(r0, r1, r2, r3, a);
                MMA(sc[j], qa[2 * s2],     r0, r1);
                MMA(sc[j], qa[2 * s2 + 1], r2, r3);
            }
        }

        // ---------- exp + C-frag -> A-frag conversion (quad shuffles) ----------
        uint32_t pa[8][4];
#pragma unroll
        for (int j = 0; j < 8; j++) {
            float e0 = __expf(sc[j][0]);
            float e1 = __expf(sc[j][1]);
            float e2 = __expf(sc[j][2]);
            float e3 = __expf(sc[j][3]);
            rs0 += e0 + e1;
            rs1 += e2 + e3;
            float x0 = __shfl_sync(0xffffffffu, e0, src_lo);
            float x1 = __shfl_sync(0xffffffffu, e1, src_lo);
            float y0 = __shfl_sync(0xffffffffu, e0, src_hi);
            float y1 = __shfl_sync(0xffffffffu, e1, src_hi);
            float x2 = __shfl_sync(0xffffffffu, e2, src_lo);
            float x3 = __shfl_sync(0xffffffffu, e3, src_lo);
            float y2 = __shfl_sync(0xffffffffu, e2, src_hi);
            float y3 = __shfl_sync(0xffffffffu, e3, src_hi);
            pa[j][0] = cvt_tf32(sel ? x1 : x0);   // row r0,  k = q4
            pa[j][2] = cvt_tf32(sel ? y1 : y0);   // row r0,  k = q4+4
            pa[j][1] = cvt_tf32(sel ? x3 : x2);   // row r0+8, k = q4
            pa[j][3] = cvt_tf32(sel ? y3 : y2);   // row r0+8, k = q4+4
        }

        // ---------- GEMM2: O[16m x 128d] += P . V^T ----------
#pragma unroll
        for (int j = 0; j < 16; j++) {
#pragma unroll
            for (int s2 = 0; s2 < 4; s2++) {
                uint32_t r0, r1, r2, r3;
                uint32_t a = vb + (8 * j + lr) * 256 +
                             (uint32_t)((((4 * s2 + hi) ^ lr)) << 4);
                LDSM4(r0, r1, r2, r3, a);
                MMA(oc[j], pa[2 * s2],     r0, r1);
                MMA(oc[j], pa[2 * s2 + 1], r2, r3);
            }
        }

        __syncthreads();          // all warps done reading buffer b
        if (i + 2 < NIT) { loadK(i + 2, b); loadV(i + 2, b); }
        CP_COMMIT();
    }

    // ---------- epilogue: write unnormalized O and row sums ----------
    {
        const int r0 = w * 16 + (lane >> 2);
        float* gO = &g_O[(size_t)(zs * 64 + hm) * 128 * 128];
#pragma unroll
        for (int j = 0; j < 16; j++) {
            int d0 = 8 * j + 2 * q4;
            *reinterpret_cast<float2*>(gO + (size_t)r0 * 128 + d0) =
                make_float2(oc[j][0], oc[j][1]);
            *reinterpret_cast<float2*>(gO + (size_t)(r0 + 8) * 128 + d0) =
                make_float2(oc[j][2], oc[j][3]);
        }
        rs0 += __shfl_xor_sync(0xffffffffu, rs0, 1);
        rs0 += __shfl_xor_sync(0xffffffffu, rs0, 2);
        rs1 += __shfl_xor_sync(0xffffffffu, rs1, 1);
        rs1 += __shfl_xor_sync(0xffffffffu, rs1, 2);
        if (q4 == 0) {
            g_R[(size_t)(zs * 64 + hm) * 128 + r0]     = rs0;
            g_R[(size_t)(zs * 64 + hm) * 128 + r0 + 8] = rs1;
        }
    }
}

// ============================================================
// combine: merge the two z-splits and normalize
// ============================================================
__global__ void __launch_bounds__(128)
kvmem_combine(float* __restrict__ out) {
    int rowg = blockIdx.x;               // 0..8191
    int hm = rowg >> 7, m = rowg & 127;
    int head = hm >> 3, mt = hm & 7;
    float rs = g_R[(size_t)hm * 128 + m] + g_R[(size_t)(64 + hm) * 128 + m];
    float inv = 1.0f / rs;
    const float* o0 = &g_O[((size_t)hm * 128 + m) * 128];
    const float* o1 = &g_O[(((size_t)64 + hm) * 128 + m) * 128];
    float* o = out + (size_t)(mt * 128 + m) * MEMDIM + head * 128;
    int d = threadIdx.x;
    o[d] = (o0[d] + o1[d]) * inv;
}

extern "C" void kernel_launch(void* const* d_in, const int* in_sizes, int n_in,
                              void* d_out, int out_size) {
    const float* hin    = (const float*)d_in[0];
    const float* keys   = (const float*)d_in[1];
    const float* values = (const float*)d_in[2];
    float* out = (float*)d_out;
    cudaFuncSetAttribute(kvmem_main, cudaFuncAttributeMaxDynamicSharedMemorySize, SMEM_BYTES);
    kvmem_main<<<128, 256, SMEM_BYTES>>>(hin, keys, values);
    kvmem_combine<<<8192, 128>>>(out);
}

// round 5
// speedup vs baseline: 1.9780x; 1.9780x over previous
#include <cuda_runtime.h>
#include <cuda_fp16.h>
#include <cstdint>
#include <cstddef>

#define NHEADS   8
#define MEMDIM   1024
#define MEMSIZE  32768
#define TZ       64
#define ZSPLIT   2
#define ZPER     (MEMSIZE / ZSPLIT)   // 16384
#define NIT      (ZPER / TZ)          // 256

// smem layout (fp16 tiles)
#define OFF_K0   0u
#define OFF_K1   16384u
#define OFF_V0   32768u
#define OFF_V1   49152u
#define OFF_Q    65536u
#define SMEM_BYTES (65536u + 32768u)   // 96 KB

// fp16 copies of the inputs (filled by prepass each launch)
__device__ __half g_Qh[1024 * 1024];
__device__ __half g_Kh[(size_t)MEMSIZE * MEMDIM];
__device__ __half g_Vh[(size_t)MEMDIM * MEMSIZE];

__device__ float g_O[ZSPLIT * 64 * 128 * 128];   // [zs*64+hm][m][d] unnormalized
__device__ float g_R[ZSPLIT * 64 * 128];         // row sums

// ---------------- helpers ----------------
__device__ __forceinline__ uint32_t smem_u32(const void* p) {
    uint32_t a;
    asm("{ .reg .u64 t; cvta.to.shared.u64 t, %1; cvt.u32.u64 %0, t; }" : "=r"(a) : "l"(p));
    return a;
}

#define CP16(dst, src) \
    asm volatile("cp.async.cg.shared.global [%0], [%1], 16;" :: "r"(dst), "l"(src) : "memory")
#define CP_COMMIT() asm volatile("cp.async.commit_group;" ::: "memory")
#define CP_WAIT(n)  asm volatile("cp.async.wait_group %0;" :: "n"(n) : "memory")

#define LDSM4(r0, r1, r2, r3, a) \
    asm volatile("ldmatrix.sync.aligned.m8n8.x4.shared.b16 {%0,%1,%2,%3}, [%4];" \
        : "=r"(r0), "=r"(r1), "=r"(r2), "=r"(r3) : "r"(a))

#define MMAH(c, a0, a1, a2, a3, b0, b1) \
    asm volatile("mma.sync.aligned.m16n8k16.row.col.f32.f16.f16.f32 " \
        "{%0,%1,%2,%3}, {%4,%5,%6,%7}, {%8,%9}, {%0,%1,%2,%3};" \
        : "+f"((c)[0]), "+f"((c)[1]), "+f"((c)[2]), "+f"((c)[3]) \
        : "r"(a0), "r"(a1), "r"(a2), "r"(a3), "r"(b0), "r"(b1))

__device__ __forceinline__ uint32_t packh2(float lo, float hi) {
    __half2 h = __floats2half2_rn(lo, hi);
    return *reinterpret_cast<uint32_t*>(&h);
}

// ============================================================
// prepass: f32 -> fp16 copies of h, keys, values
// ============================================================
__global__ void __launch_bounds__(256)
kvmem_prepass(const float* __restrict__ hin, const float* __restrict__ keys,
              const float* __restrict__ values) {
    const size_t NQ4 = (size_t)1024 * 1024 / 4;          // 262144
    const size_t NK4 = (size_t)MEMSIZE * MEMDIM / 4;     // 8388608
    const size_t NV4 = NK4;
    const size_t TOT = NQ4 + NK4 + NV4;
    size_t stride = (size_t)gridDim.x * blockDim.x;
    for (size_t i = (size_t)blockIdx.x * blockDim.x + threadIdx.x; i < TOT; i += stride) {
        const float4* src;
        uint2* dst;
        size_t off;
        if (i < NQ4) {
            src = (const float4*)hin; dst = (uint2*)g_Qh; off = i;
        } else if (i < NQ4 + NK4) {
            src = (const float4*)keys; dst = (uint2*)g_Kh; off = i - NQ4;
        } else {
            src = (const float4*)values; dst = (uint2*)g_Vh; off = i - NQ4 - NK4;
        }
        float4 v = src[off];
        uint2 u;
        u.x = packh2(v.x, v.y);
        u.y = packh2(v.z, v.w);
        dst[off] = u;
    }
}

// ============================================================
// main kernel: one CTA = (zsplit, head, mtile); 256 threads
// ============================================================
__global__ void __launch_bounds__(256, 1)
kvmem_main() {
    extern __shared__ __align__(1024) char dsm[];
    const uint32_t base = smem_u32(dsm);

    const int tid  = threadIdx.x;
    const int lane = tid & 31;
    const int w    = tid >> 5;

    const int cta  = blockIdx.x;          // 0..127
    const int zs   = cta >> 6;
    const int hm   = cta & 63;
    const int head = hm >> 3, mt = hm & 7;
    const int z0base = zs * ZPER;
    const int tok0   = mt * 128;

    const uint32_t Kb[2] = { base + OFF_K0, base + OFF_K1 };
    const uint32_t Vb[2] = { base + OFF_V0, base + OFF_V1 };
    const uint32_t Qs    = base + OFF_Q;

    // ---------- prologue: stage Q fp16 (128 rows x 256B, swizzled) ----------
    {
        const __half* qsrc = g_Qh + (size_t)tok0 * MEMDIM + head * 128;
#pragma unroll
        for (int c = tid; c < 2048; c += 256) {
            int m = c >> 4, ch = c & 15;
            uint32_t dst = Qs + m * 256 + (uint32_t)((ch ^ (m & 7)) << 4);
            CP16(dst, qsrc + (size_t)m * MEMDIM + ch * 8);
        }
        CP_COMMIT();
    }

    auto loadK = [&](int it, int b) {
        const __half* ksrc = g_Kh + (size_t)(z0base + it * TZ) * MEMDIM + head * 128;
#pragma unroll
        for (int c = tid; c < 1024; c += 256) {
            int z = c >> 4, ch = c & 15;                  // 64 rows x 256B
            uint32_t dst = Kb[b] + z * 256 + (uint32_t)((ch ^ (z & 7)) << 4);
            CP16(dst, ksrc + (size_t)z * MEMDIM + ch * 8);
        }
    };
    auto loadV = [&](int it, int b) {
        const __half* vsrc = g_Vh + (size_t)(head * 128) * MEMSIZE + z0base + it * TZ;
#pragma unroll
        for (int c = tid; c < 1024; c += 256) {
            int d = c >> 3, ch = c & 7;                   // 128 rows x 128B
            uint32_t dst = Vb[b] + d * 128 + (uint32_t)((ch ^ (d & 7)) << 4);
            CP16(dst, vsrc + (size_t)d * MEMSIZE + ch * 8);
        }
    };

    loadK(0, 0); loadV(0, 0); CP_COMMIT();
    loadK(1, 1); loadV(1, 1); CP_COMMIT();

    // ---------- Q a-frags (8 k16-steps x 4 regs) ----------
    uint32_t qa[8][4];
    CP_WAIT(2);                 // Q landed
    __syncthreads();
    {
        const int row = w * 16 + ((lane >> 3) & 1) * 8 + (lane & 7);
        const int cb  = lane >> 4;
#pragma unroll
        for (int s = 0; s < 8; s++) {
            int ch = 2 * s + cb;
            uint32_t a = Qs + row * 256 + (uint32_t)((ch ^ (row & 7)) << 4);
            LDSM4(qa[s][0], qa[s][1], qa[s][2], qa[s][3], a);
        }
    }

    // O^T accumulators: [u: d-tile][h: m_q half][4]
    float oc[8][2][4];
#pragma unroll
    for (int u = 0; u < 8; u++)
#pragma unroll
        for (int h = 0; h < 2; h++) { oc[u][h][0] = oc[u][h][1] = oc[u][h][2] = oc[u][h][3] = 0.f; }
    float rs0 = 0.f, rs1 = 0.f;

    // lane-derived addressing constants
    const int krow_off = ((lane >> 4) << 3) + (lane & 7);   // B x4: tiles 0,1 = n-block jp*2; 2,3 = jp*2+1
    const int kch_off  = (lane >> 3) & 1;
    const int vrow_off = ((lane >> 3) & 1) * 8 + (lane & 7); // A x4 pattern
    const int vch_off  = lane >> 4;

#pragma unroll 1
    for (int i = 0; i < NIT; i++) {
        const int b = i & 1;
        CP_WAIT(1);
        __syncthreads();
        const uint32_t kb = Kb[b], vb = Vb[b];

        // ---------- GEMM1: S[16m x 64z] = Q . K^T ----------
        float sc[8][4];
#pragma unroll
        for (int j = 0; j < 8; j++) { sc[j][0] = sc[j][1] = sc[j][2] = sc[j][3] = 0.f; }
#pragma unroll
        for (int jp = 0; jp < 4; jp++) {
#pragma unroll
            for (int s = 0; s < 8; s++) {
                int row = 16 * jp + krow_off;
                int ch  = 2 * s + kch_off;
                uint32_t a = kb + row * 256 + (uint32_t)((ch ^ (row & 7)) << 4);
                uint32_t r0, r1, r2, r3;
                LDSM4(r0, r1, r2, r3, a);
                MMAH(sc[2 * jp],     qa[s][0], qa[s][1], qa[s][2], qa[s][3], r0, r1);
                MMAH(sc[2 * jp + 1], qa[s][0], qa[s][1], qa[s][2], qa[s][3], r2, r3);
            }
        }

        // ---------- exp + pack into B-frags of P^T (no shuffles!) ----------
        uint32_t plo[8], phi[8];
#pragma unroll
        for (int j = 0; j < 8; j++) {
            float e0 = __expf(sc[j][0]);
            float e1 = __expf(sc[j][1]);
            float e2 = __expf(sc[j][2]);
            float e3 = __expf(sc[j][3]);
            rs0 += e0 + e1;
            rs1 += e2 + e3;
            plo[j] = packh2(e0, e1);    // rows m=t/4,   k = z pair
            phi[j] = packh2(e2, e3);    // rows m=t/4+8
        }

        // ---------- GEMM2: O^T[128d x 16m] += V . P^T ----------
#pragma unroll
        for (int u = 0; u < 8; u++) {
#pragma unroll
            for (int s = 0; s < 4; s++) {
                int row = 16 * u + vrow_off;
                int ch  = 2 * s + vch_off;
                uint32_t a = vb + row * 128 + (uint32_t)((ch ^ (row & 7)) << 4);
                uint32_t a0, a1, a2, a3;
                LDSM4(a0, a1, a2, a3, a);
                MMAH(oc[u][0], a0, a1, a2, a3, plo[2 * s], plo[2 * s + 1]);
                MMAH(oc[u][1], a0, a1, a2, a3, phi[2 * s], phi[2 * s + 1]);
            }
        }

        __syncthreads();          // all warps done reading buffer b
        if (i + 2 < NIT) { loadK(i + 2, b); loadV(i + 2, b); }
        CP_COMMIT();
    }

    // ---------- epilogue: transpose O^T -> O via smem, write g_O ----------
    __syncthreads();
    {
        // write O^T frags into smem as O[m][d] (f32, 128 rows x 512B, swizzled)
        const int dq = lane >> 2;           // d within tile
        const int mq = 2 * (lane & 3);      // m_q col pair base
#pragma unroll
        for (int u = 0; u < 8; u++) {
#pragma unroll
            for (int h = 0; h < 2; h++) {
                int d0 = 16 * u + dq;
                int m0 = w * 16 + 8 * h + mq;
#pragma unroll
                for (int e = 0; e < 4; e++) {
                    int d = d0 + (e >> 1) * 8;       // c2,c3 are d+8
                    int m = m0 + (e & 1);
                    uint32_t adr = base + m * 512 +
                                   (uint32_t)((((d >> 2) ^ (m & 7)) << 4) + (d & 3) * 4);
                    asm volatile("st.shared.b32 [%0], %1;" :: "r"(adr), "f"(oc[u][h][e]) : "memory");
                }
            }
        }
    }
    __syncthreads();
    {
        int m = tid >> 1, half = tid & 1;
        float* gO = &g_O[(size_t)(zs * 64 + hm) * 16384 + (size_t)m * 128];
#pragma unroll
        for (int c = 0; c < 16; c++) {
            int ch = half * 16 + c;
            uint32_t adr = base + m * 512 + (uint32_t)((ch ^ (m & 7)) << 4);
            float4 v;
            asm volatile("ld.shared.v4.f32 {%0,%1,%2,%3}, [%4];"
                         : "=f"(v.x), "=f"(v.y), "=f"(v.z), "=f"(v.w) : "r"(adr));
            *reinterpret_cast<float4*>(gO + ch * 4) = v;
        }
    }
    // row sums (quad-reduce: lanes in a quad hold same row's partial sums)
    rs0 += __shfl_xor_sync(0xffffffffu, rs0, 1);
    rs0 += __shfl_xor_sync(0xffffffffu, rs0, 2);
    rs1 += __shfl_xor_sync(0xffffffffu, rs1, 1);
    rs1 += __shfl_xor_sync(0xffffffffu, rs1, 2);
    if ((lane & 3) == 0) {
        int r0 = w * 16 + (lane >> 2);
        g_R[(size_t)(zs * 64 + hm) * 128 + r0]     = rs0;
        g_R[(size_t)(zs * 64 + hm) * 128 + r0 + 8] = rs1;
    }
}

// ============================================================
// combine: merge the two z-splits and normalize
// ============================================================
__global__ void __launch_bounds__(128)
kvmem_combine(float* __restrict__ out) {
    int rowg = blockIdx.x;               // 0..8191
    int hm = rowg >> 7, m = rowg & 127;
    int head = hm >> 3, mt = hm & 7;
    float rs = g_R[(size_t)hm * 128 + m] + g_R[(size_t)(64 + hm) * 128 + m];
    float inv = 1.0f / rs;
    const float* o0 = &g_O[((size_t)hm * 128 + m) * 128];
    const float* o1 = &g_O[(((size_t)64 + hm) * 128 + m) * 128];
    float* o = out + (size_t)(mt * 128 + m) * MEMDIM + head * 128;
    int d = threadIdx.x;
    o[d] = (o0[d] + o1[d]) * inv;
}

extern "C" void kernel_launch(void* const* d_in, const int* in_sizes, int n_in,
                              void* d_out, int out_size) {
    const float* hin    = (const float*)d_in[0];
    const float* keys   = (const float*)d_in[1];
    const float* values = (const float*)d_in[2];
    float* out = (float*)d_out;
    kvmem_prepass<<<1184, 256>>>(hin, keys, values);
    cudaFuncSetAttribute(kvmem_main, cudaFuncAttributeMaxDynamicSharedMemorySize, SMEM_BYTES);
    kvmem_main<<<128, 256, SMEM_BYTES>>>();
    kvmem_combine<<<8192, 128>>>(out);
}